// round 15
// baseline (speedup 1.0000x reference)
#include <cuda_runtime.h>
#include <cuda_fp16.h>
#include <cstdint>

// ---------------- problem constants ----------------
#define N_VOX 200000
#define NI    64
#define NF    128
#define NE    256
#define NB    16
#define KTAP  27
#define KDOWN 8
#define NDOWN 25000
#define EPSBN 1e-5f
#define WSC   32.0f
#define WSCI  (1.0f / 32.0f)

#define TM 128
#define CG1 1563                      // conv tile count over N_VOX
#define SWZ(o) ((o) ^ ((((o) >> 3)) & 0x70))

typedef unsigned long long u64;

// ---------------- device scratch ----------------
__device__ __half g_x16[(size_t)N_VOX * NI];   // fp16(x) for idconv
__device__ __half g_y1 [(size_t)N_VOX * NI];   // fp16 bn_silu(x)
__device__ __half g_y2 [(size_t)N_VOX * NF];   // fp16 bn_silu(h)
__device__ __half g_h2 [(size_t)N_VOX * NF];   // fp16 conv2+idconv out
__device__ __half g_h16[(size_t)N_VOX * NF];   // fp16 conv1 out
// weight tiles: 16384 B each, pre-swizzled K-major [n=128][k=64] fp16, scaled x32
__device__ uint4 g_w1[27 * 1024];
__device__ uint4 g_w2[54 * 1024];
__device__ uint4 g_wi[1024];
__device__ uint4 g_wd[16 * 1024];
__device__ float g_psum[256 * NF], g_psq[256 * NF];
__device__ float g_ps[(size_t)CG1 * NF], g_pq[(size_t)CG1 * NF];  // per-CTA BN2 partials
__device__ float g_mean[NF], g_rstd[NF];
__device__ float g_tp[NB * NE];
__device__ unsigned g_ctr1;                    // last-block counter (self-resetting)

// ---------------- PTX helpers ----------------
__device__ __forceinline__ uint32_t s2u(const void* p) {
    uint32_t a;
    asm("{ .reg .u64 t; cvta.to.shared.u64 t, %1; cvt.u32.u64 %0, t; }" : "=r"(a) : "l"(p));
    return a;
}
__device__ __forceinline__ void cp16(uint32_t dst, const void* src, uint32_t bytes) {
    asm volatile("cp.async.cg.shared.global [%0], [%1], 16, %2;"
                 :: "r"(dst), "l"(src), "r"(bytes) : "memory");
}
__device__ __forceinline__ void ldsm4(uint32_t* r, uint32_t a) {
    asm volatile("ldmatrix.sync.aligned.m8n8.x4.shared.b16 {%0,%1,%2,%3}, [%4];"
                 : "=r"(r[0]), "=r"(r[1]), "=r"(r[2]), "=r"(r[3]) : "r"(a));
}
__device__ __forceinline__ void mma16816(float* c, const uint32_t* a, const uint32_t* b) {
    asm volatile(
        "mma.sync.aligned.m16n8k16.row.col.f32.f16.f16.f32 "
        "{%0,%1,%2,%3}, {%4,%5,%6,%7}, {%8,%9}, {%0,%1,%2,%3};"
        : "+f"(c[0]), "+f"(c[1]), "+f"(c[2]), "+f"(c[3])
        : "r"(a[0]), "r"(a[1]), "r"(a[2]), "r"(a[3]), "r"(b[0]), "r"(b[1]));
}
__device__ __forceinline__ float silu_f(float z) { return z / (1.0f + __expf(-z)); }

// ---------------- weight transform core ----------------
__device__ __forceinline__ void w_xform(const float* __restrict__ W, __half* __restrict__ oh,
                                        int e, int CI) {
    int n = e & 127, c = (e >> 7) % CI, t = e / (CI * 128);
    int tile = t * (CI >> 6) + (c >> 6);
    uint32_t sw = SWZ((uint32_t)(n * 128 + (c & 63) * 2));
    oh[(size_t)tile * 8192 + (sw >> 1)] = __float2half(W[e] * WSC);
}

// ---------------- fused: prep W1 + time-embedding projection ----------------
#define W1_BLOCKS 864                           // 27*64*128/256
__global__ void prep_w1_tproj(const float* __restrict__ W1, __half* __restrict__ o1,
                              const float* __restrict__ t, const float* __restrict__ Wt,
                              const float* __restrict__ bt) {
    __shared__ float st[NE];
    __shared__ float red[8][32];
    int bid = blockIdx.x;
    int tid = threadIdx.x;
    if (bid < W1_BLOCKS) {
        w_xform(W1, o1, bid * 256 + tid, 64);   // 864*256 == 27*64*128 exactly
        return;
    }
    int tb = bid - W1_BLOCKS;                   // 0..127
    int b = tb >> 3, yq = tb & 7;
    st[tid] = silu_f(t[b * NE + tid]);
    __syncthreads();
    int col = yq * 32 + (tid & 31);
    int sl = tid >> 5;
    float acc = 0.f;
    #pragma unroll
    for (int e = 0; e < 32; e++) acc += st[sl * 32 + e] * Wt[(sl * 32 + e) * (2 * NF) + col];
    red[sl][tid & 31] = acc;
    __syncthreads();
    if (sl == 0) {
        float s = 0.f;
        #pragma unroll
        for (int i = 0; i < 8; i++) s += red[i][tid & 31];
        g_tp[b * NE + col] = s + bt[col];
    }
}

// batched: W2 (27x128x128) + Wid (64x128) + Wd (8x128x128) in one launch
#define W2_E  (27 * 128 * 128)
#define WI_E  (64 * 128)
#define WD_E  (8 * 128 * 128)
__global__ void prep_w3(const float* __restrict__ W2, const float* __restrict__ Wid,
                        const float* __restrict__ Wd,
                        __half* __restrict__ o2, __half* __restrict__ oi,
                        __half* __restrict__ od) {
    int e = blockIdx.x * blockDim.x + threadIdx.x;
    if (e < W2_E) { w_xform(W2, o2, e, 128); return; }
    e -= W2_E;
    if (e < WI_E) { w_xform(Wid, oi, e, 64); return; }
    e -= WI_E;
    if (e < WD_E) w_xform(Wd, od, e, 128);
}

// ---------------- BN1 stats: grid reduce + last-block finalize (one launch) ----------------
template<int C>
__global__ void bn_reduce_fused(const float* __restrict__ v, int nrows) {
    const int COPIES = 256 / C;
    int tid = threadIdx.x, c = tid % C, slot = tid / C;
    int rpb = (nrows + gridDim.x - 1) / gridDim.x;
    int r0 = blockIdx.x * rpb, r1 = min(r0 + rpb, nrows);
    float s = 0.f, q = 0.f;
    for (int r = r0 + slot; r < r1; r += COPIES) {
        float val = v[(size_t)r * C + c];
        s += val; q += val * val;
    }
    __shared__ float ss[256], sq[256];
    ss[tid] = s; sq[tid] = q;
    __syncthreads();
    if (slot == 0) {
        #pragma unroll
        for (int i = 1; i < COPIES; i++) { s += ss[i * C + c]; q += sq[i * C + c]; }
        g_psum[blockIdx.x * C + c] = s;
        g_psq [blockIdx.x * C + c] = q;
    }
    // last-block finalize
    __threadfence();
    __shared__ bool last;
    if (tid == 0) last = (atomicAdd(&g_ctr1, 1u) == gridDim.x - 1);
    __syncthreads();
    if (!last) return;
    float fs = 0.f, fq = 0.f;
    for (int i = slot; i < 256; i += COPIES) {
        fs += g_psum[i * C + c];
        fq += g_psq [i * C + c];
    }
    ss[tid] = fs; sq[tid] = fq;
    __syncthreads();
    if (slot == 0) {
        #pragma unroll
        for (int i = 1; i < COPIES; i++) { fs += ss[i * C + c]; fq += sq[i * C + c]; }
        float m = fs / (float)nrows;
        g_mean[c] = m;
        g_rstd[c] = rsqrtf(fq / (float)nrows - m * m + EPSBN);
    }
    if (tid == 0) g_ctr1 = 0;                   // reset for next graph replay
}

// ---------------- BN2 stats: reduce per-CTA partials + finalize ----------------
__global__ void bn2_stats(int nrows) {
    int tid = threadIdx.x;              // 1024
    int c = tid & 127, slot = tid >> 7; // 8 slots
    float s = 0.f, q = 0.f;
    for (int r = slot; r < CG1; r += 8) {
        s += g_ps[(size_t)r * NF + c];
        q += g_pq[(size_t)r * NF + c];
    }
    __shared__ float ss[1024], sq[1024];
    ss[tid] = s; sq[tid] = q;
    __syncthreads();
    if (slot == 0) {
        #pragma unroll
        for (int i = 1; i < 8; i++) { s += ss[i * 128 + c]; q += sq[i * 128 + c]; }
        float m = s / (float)nrows;
        g_mean[c] = m;
        g_rstd[c] = rsqrtf(q / (float)nrows - m * m + EPSBN);
    }
}

// ---------------- fused: x -> fp16 copy + BN1+SiLU -> y1 ----------------
__global__ void prep_x(const float* __restrict__ v, __half* __restrict__ x16,
                       __half* __restrict__ y1, const float* __restrict__ g,
                       const float* __restrict__ be, size_t nelem) {
    size_t i = ((size_t)blockIdx.x * blockDim.x + threadIdx.x) * 4;
    if (i >= nelem) return;
    float4 x = *(const float4*)(v + i);
    *(__half2*)(x16 + i)     = __floats2half2_rn(x.x, x.y);
    *(__half2*)(x16 + i + 2) = __floats2half2_rn(x.z, x.w);
    int c = (int)(i & (size_t)(NI - 1));
    float t[4] = {x.x, x.y, x.z, x.w};
    #pragma unroll
    for (int j = 0; j < 4; j++) {
        int cc = c + j;
        t[j] = silu_f((t[j] - g_mean[cc]) * g_rstd[cc] * g[cc] + be[cc]);
    }
    *(__half2*)(y1 + i)     = __floats2half2_rn(t[0], t[1]);
    *(__half2*)(y1 + i + 2) = __floats2half2_rn(t[2], t[3]);
}

// ---------------- BN2 apply + SiLU on fp16 h -> fp16 y2 ----------------
__global__ void bn_silu_h16(const __half* __restrict__ v, __half* __restrict__ o,
                            const float* __restrict__ g, const float* __restrict__ be,
                            size_t nelem) {
    size_t i = ((size_t)blockIdx.x * blockDim.x + threadIdx.x) * 8;
    if (i >= nelem) return;
    uint4 raw = *(const uint4*)(v + i);
    __half2* hp = (__half2*)&raw;
    int c = (int)(i & (size_t)(NF - 1));
    uint4 outr;
    __half2* op = (__half2*)&outr;
    #pragma unroll
    for (int j = 0; j < 4; j++) {
        float2 f = __half22float2(hp[j]);
        int c0 = c + 2 * j, c1 = c0 + 1;
        f.x = silu_f((f.x - g_mean[c0]) * g_rstd[c0] * g[c0] + be[c0]);
        f.y = silu_f((f.y - g_mean[c1]) * g_rstd[c1] * g[c1] + be[c1]);
        op[j] = __floats2half2_rn(f.x, f.y);
    }
    *(uint4*)(o + i) = outr;
}

// ---------------- HMMA gather-GEMM conv (single-pass fp16, k-pipelined) ----------------
// EPI 0: out = acc/32                    (down conv, fp32 out)
// EPI 1: out = (1+sc)*(acc/32+b1) + sh   (conv1 + TE, fp16 out + BN2 partial stats)
// EPI 2: out = acc/32 + b2 + bid         (conv2 + idconv tap, fp16 out)
#define BUF_SZ 32768
#define NSTAGE 3
template<int NCH, int NTAPS, int EPI>
__global__ __launch_bounds__(256, 2)
void conv_mma(const __half* __restrict__ ain, const uint4* __restrict__ wh,
              const int* __restrict__ nbr, int nrows,
              float* __restrict__ outf, __half* __restrict__ outh,
              const float* __restrict__ bias, const float* __restrict__ bias2,
              const int* __restrict__ b_idx, const float* __restrict__ tp,
              const __half* __restrict__ xh, const uint4* __restrict__ wih) {
    extern __shared__ __align__(1024) char smem[];
    constexpr int NIT = NTAPS * NCH + (EPI == 2 ? 1 : 0);
    constexpr int IDXB = ((NTAPS * 512 + 1023) / 1024) * 1024;   // idx region bytes
    const int tid = threadIdx.x;
    const int wid = tid >> 5;
    const int lane = tid & 31;
    int* idx_s = (int*)smem;
    const uint32_t sbase = s2u(smem);
    const uint32_t tiles = sbase + IDXB;    // stage s at +s*BUF_SZ: A(16K), B(16K)
    const int row0 = blockIdx.x * TM;

    // loader indices
    const int lrow = tid >> 1;
    const int lq0 = (tid & 1) * 4;

    // compute indices
    const int mrow0 = (wid >> 1) * 32;
    const int ncol0 = (wid & 1) * 64;
    const int gID = lane >> 2, tig = lane & 3;
    const int rA = mrow0 + (lane & 15);
    const uint32_t aRowOff = (uint32_t)rA * 128u;
    const int selA = rA & 7;
    const int aC0 = lane >> 4;
    const int nB = (lane & 7) + ((lane >> 4) & 1) * 8;
    const int selB = lane & 7;
    const int bKpar = (lane >> 3) & 1;

    float acc[2][8][4];
    #pragma unroll
    for (int i = 0; i < 2; i++)
        #pragma unroll
        for (int j = 0; j < 8; j++)
            #pragma unroll
            for (int k = 0; k < 4; k++) acc[i][j][k] = 0.f;

    // ---- prologue: preload ALL tap indices for this tile into smem ----
    {
        const int NCHK = NTAPS * 32;
        for (int c = tid; c < NCHK; c += 256) {
            int tap = c >> 5, cw = c & 31;
            int r0c = row0 + cw * 4;
            int rem = nrows - r0c;
            uint32_t bytes = rem <= 0 ? 0u : (rem >= 4 ? 16u : (uint32_t)rem * 4u);
            cp16(sbase + (uint32_t)c * 16u, nbr + (size_t)tap * nrows + r0c, bytes);
        }
        asm volatile("cp.async.commit_group;" ::: "memory");
        asm volatile("cp.async.wait_group 0;" ::: "memory");
        __syncthreads();
    }

    auto load_it = [&](int it, uint32_t stage) {
        uint32_t tb = tiles + stage * BUF_SZ;
        const __half* sa; int ci, coff, idx;
        const uint4* bh_;
        if (EPI == 2 && it == NTAPS * NCH) {             // idconv tap
            int r = row0 + lrow;
            sa = xh; ci = NI; coff = 0;
            idx = (r < N_VOX) ? r : -1;
            bh_ = wih;
        } else {
            int tap = (NCH == 1) ? it : (it >> 1);
            sa = ain; ci = NCH * 64; coff = (NCH == 1) ? 0 : (it & 1) * 64;
            idx = idx_s[tap * 128 + lrow];
            bh_ = wh + (size_t)it * 1024;
        }
        uint32_t ok = (idx >= 0) ? 16u : 0u;
        size_t abase = (size_t)(idx >= 0 ? idx : 0) * ci + coff + lq0 * 8;
        #pragma unroll
        for (int q = 0; q < 4; q++) {
            uint32_t so = SWZ((uint32_t)(lrow * 128 + (lq0 + q) * 16));
            cp16(tb + so, sa + abase + q * 8, ok);
        }
        #pragma unroll
        for (int i = 0; i < 4; i++) {
            uint32_t so = (uint32_t)(tid * 16 + i * 4096);
            cp16(tb + 16384 + so, bh_ + tid + i * 256, 16u);
        }
        asm volatile("cp.async.commit_group;" ::: "memory");
    };

    // fragment loaders (ks-indexed)
    auto ldA = [&](uint32_t* dst, uint32_t tb, int ks) {
        #pragma unroll
        for (int mt = 0; mt < 2; mt++) {
            uint32_t off = aRowOff + (uint32_t)mt * 2048u +
                           ((uint32_t)((aC0 + ks * 2) ^ selA) << 4);
            ldsm4(dst + mt * 4, tb + off);
        }
    };
    auto ldB = [&](uint32_t* dst, uint32_t tb, int ks) {
        #pragma unroll
        for (int p = 0; p < 4; p++) {
            uint32_t off = (uint32_t)(ncol0 + p * 16 + nB) * 128u +
                           ((uint32_t)((ks * 2 + bKpar) ^ selB) << 4);
            ldsm4(dst + p * 4, tb + 16384 + off);
        }
    };

    uint32_t st = 0;
    load_it(0, 0);
    if (NIT > 1) load_it(1, 1);
    for (int it = 0; it < NIT; ++it) {
        if (it + 2 < NIT) asm volatile("cp.async.wait_group 1;" ::: "memory");
        else              asm volatile("cp.async.wait_group 0;" ::: "memory");
        __syncthreads();
        if (it + 2 < NIT) {
            uint32_t s2 = st + 2; if (s2 >= NSTAGE) s2 -= NSTAGE;
            load_it(it + 2, s2);
        }
        uint32_t tb = tiles + st * BUF_SZ;

        // ---- k-pipelined fragment loop: ldsm(ks+1) issued before mma(ks) ----
        uint32_t Af[2][8], Bf[2][16];
        ldA(Af[0], tb, 0);
        ldB(Bf[0], tb, 0);
        #pragma unroll
        for (int ks = 0; ks < 4; ks++) {
            const int cur = ks & 1, nxt = cur ^ 1;
            if (ks < 3) {
                ldA(Af[nxt], tb, ks + 1);
                ldB(Bf[nxt], tb, ks + 1);
            }
            #pragma unroll
            for (int mt = 0; mt < 2; mt++)
                #pragma unroll
                for (int nt = 0; nt < 8; nt++)
                    mma16816(acc[mt][nt], &Af[cur][mt * 4],
                             &Bf[cur][(nt >> 1) * 4 + (nt & 1) * 2]);
        }
        if (++st == NSTAGE) st = 0;
    }

    // ---------------- epilogue ----------------
    if (EPI == 1) {
        float cs[16], cq[16];
        #pragma unroll
        for (int j = 0; j < 16; j++) { cs[j] = 0.f; cq[j] = 0.f; }
        #pragma unroll
        for (int mt = 0; mt < 2; mt++) {
            int rl = row0 + mrow0 + mt * 16 + gID;
            #pragma unroll
            for (int hh = 0; hh < 2; hh++) {
                int r = rl + hh * 8;
                if (r < nrows) {
                    const float* sp = tp + (size_t)__ldg(&b_idx[r]) * NE;
                    #pragma unroll
                    for (int nt = 0; nt < 8; nt++) {
                        int c = ncol0 + nt * 8 + 2 * tig;
                        float v0 = acc[mt][nt][hh * 2] * WSCI;
                        float v1 = acc[mt][nt][hh * 2 + 1] * WSCI;
                        v0 = (1.f + __ldg(sp + c)) * (v0 + __ldg(bias + c)) + __ldg(sp + NF + c);
                        v1 = (1.f + __ldg(sp + c + 1)) * (v1 + __ldg(bias + c + 1)) + __ldg(sp + NF + c + 1);
                        *(__half2*)(outh + (size_t)r * NF + c) = __floats2half2_rn(v0, v1);
                        cs[nt * 2]     += v0; cq[nt * 2]     += v0 * v0;
                        cs[nt * 2 + 1] += v1; cq[nt * 2 + 1] += v1 * v1;
                    }
                }
            }
        }
        __syncthreads();
        float* ps = (float*)(smem + IDXB);     // [32][129]
        float* pq = ps + 32 * 129;
        int slot = (wid >> 1) * 8 + gID;
        #pragma unroll
        for (int j = 0; j < 16; j++) {
            int c = ncol0 + (j >> 1) * 8 + 2 * tig + (j & 1);
            ps[slot * 129 + c] = cs[j];
            pq[slot * 129 + c] = cq[j];
        }
        __syncthreads();
        if (tid < NF) {
            float s = 0.f, q = 0.f;
            #pragma unroll 8
            for (int sx = 0; sx < 32; sx++) { s += ps[sx * 129 + tid]; q += pq[sx * 129 + tid]; }
            g_ps[(size_t)blockIdx.x * NF + tid] = s;
            g_pq[(size_t)blockIdx.x * NF + tid] = q;
        }
    } else {
        #pragma unroll
        for (int mt = 0; mt < 2; mt++) {
            int rl = row0 + mrow0 + mt * 16 + gID;
            #pragma unroll
            for (int hh = 0; hh < 2; hh++) {
                int r = rl + hh * 8;
                if (r >= nrows) continue;
                #pragma unroll
                for (int nt = 0; nt < 8; nt++) {
                    int c = ncol0 + nt * 8 + 2 * tig;
                    float v0 = acc[mt][nt][hh * 2] * WSCI;
                    float v1 = acc[mt][nt][hh * 2 + 1] * WSCI;
                    if (EPI == 0) {
                        *(float2*)(outf + (size_t)r * NF + c) = make_float2(v0, v1);
                    } else {
                        float o0 = v0 + __ldg(bias + c)     + __ldg(bias2 + c);
                        float o1 = v1 + __ldg(bias + c + 1) + __ldg(bias2 + c + 1);
                        *(__half2*)(outh + (size_t)r * NF + c) = __floats2half2_rn(o0, o1);
                    }
                }
            }
        }
    }
}

// ---------------- host ----------------
template<typename T> static T* sym(const void* s) {
    void* p = nullptr;
    cudaGetSymbolAddress(&p, s);
    return (T*)p;
}

extern "C" void kernel_launch(void* const* d_in, const int* in_sizes, int n_in,
                              void* d_out, int out_size) {
    const float* x     = (const float*)d_in[0];
    const float* t     = (const float*)d_in[1];
    const int*   b_idx = (const int*)  d_in[2];
    const int*   nbr   = (const int*)  d_in[3];
    const int*   nbrd  = (const int*)  d_in[4];
    const float* g1    = (const float*)d_in[5];
    const float* be1   = (const float*)d_in[6];
    const float* W1    = (const float*)d_in[7];
    const float* b1    = (const float*)d_in[8];
    const float* Wt    = (const float*)d_in[9];
    const float* bt    = (const float*)d_in[10];
    const float* g2    = (const float*)d_in[11];
    const float* be2   = (const float*)d_in[12];
    const float* W2    = (const float*)d_in[13];
    const float* b2    = (const float*)d_in[14];
    const float* Wid   = (const float*)d_in[15];
    const float* bid   = (const float*)d_in[16];
    const float* Wd    = (const float*)d_in[17];
    float* out = (float*)d_out;

    __half* x16 = sym<__half>(g_x16);
    __half* y1  = sym<__half>(g_y1);
    __half* y2  = sym<__half>(g_y2);
    __half* h2  = sym<__half>(g_h2);
    __half* h16 = sym<__half>(g_h16);
    float*  tp  = sym<float>(g_tp);
    uint4* w1 = sym<uint4>(g_w1);
    uint4* w2 = sym<uint4>(g_w2);
    uint4* wi = sym<uint4>(g_wi);
    uint4* wd = sym<uint4>(g_wd);

    const int SMEM_27 = ((27 * 512 + 1023) / 1024) * 1024 + NSTAGE * BUF_SZ;  // 112640
    const int SMEM_8  = ((8 * 512 + 1023) / 1024) * 1024 + NSTAGE * BUF_SZ;   // 102400
    cudaFuncSetAttribute(conv_mma<1, KTAP, 1>, cudaFuncAttributeMaxDynamicSharedMemorySize, SMEM_27);
    cudaFuncSetAttribute(conv_mma<2, KTAP, 2>, cudaFuncAttributeMaxDynamicSharedMemorySize, SMEM_27);
    cudaFuncSetAttribute(conv_mma<2, KDOWN, 0>, cudaFuncAttributeMaxDynamicSharedMemorySize, SMEM_8);

    const int CG = CG1;                     // 1563
    const int DG = (NDOWN + TM - 1) / TM;   // 196

    // --- launch 1: W1 prep + time-embedding projection (fused) ---
    prep_w1_tproj<<<W1_BLOCKS + NB * 8, 256>>>(W1, (__half*)w1, t, Wt, bt);

    // --- launch 2: BN1 stats (grid reduce + last-block finalize) ---
    bn_reduce_fused<NI><<<256, 256>>>(x, N_VOX);

    // --- launch 3: x -> x16 + BN1+SiLU -> y1 ---
    {
        size_t ne = (size_t)N_VOX * NI;
        prep_x<<<(int)((ne / 4 + 255) / 256), 256>>>(x, x16, y1, g1, be1, ne);
    }

    // --- launch 4: conv1 (ncu captures the 4th launch) ---
    conv_mma<1, KTAP, 1><<<CG, 256, SMEM_27>>>(
        y1, w1, nbr, N_VOX, nullptr, h16, b1, nullptr, b_idx, tp, nullptr, nullptr);

    // --- remaining ---
    prep_w3<<<(W2_E + WI_E + WD_E + 255) / 256, 256>>>(
        W2, Wid, Wd, (__half*)w2, (__half*)wi, (__half*)wd);
    bn2_stats<<<1, 1024>>>(N_VOX);
    {
        size_t ne = (size_t)N_VOX * NF;
        bn_silu_h16<<<(int)((ne / 8 + 255) / 256), 256>>>(h16, y2, g2, be2, ne);
    }
    conv_mma<2, KTAP, 2><<<CG, 256, SMEM_27>>>(
        y2, w2, nbr, N_VOX, nullptr, h2, b2, bid, nullptr, nullptr, x16, wi);
    conv_mma<2, KDOWN, 0><<<DG, 256, SMEM_8>>>(
        h2, wd, nbrd, NDOWN, out, nullptr, nullptr, nullptr, nullptr, nullptr, nullptr, nullptr);
}